// round 13
// baseline (speedup 1.0000x reference)
#include <cuda_runtime.h>
#include <cuda_bf16.h>

// FrozenBNBStableEmbedding fused gather+dequant+LayerNorm.
// R13: R5 champion inner loop verbatim. Changes (latency-only, reg-neutral):
//  - TPW=4, grid=512: halves per-CTA setup overhead
//  - all 4 token ids + absmax scales preloaded before the token loop
//    (removes x-load + scale-load from each token's serial chain)
//  - __launch_bounds__(256,4) pins regs at 64 (occupancy guard)

#define D    1024
#define REP  16
#define TPW  4           // tokens per warp
#define EPS  1e-5f

__global__ __launch_bounds__(256, 4) void emb_ln_kernel(
    const int*   __restrict__ x,
    const int*   __restrict__ w,
    const float* __restrict__ absmax,
    const float* __restrict__ code,
    const float* __restrict__ lnw,
    const float* __restrict__ lnb,
    float*       __restrict__ out,
    int n_tokens)
{
    __shared__ float  s_code[256 * REP];  // s_code[idx*REP + slot]
    __shared__ float4 s_lnw[256];
    __shared__ float4 s_lnb[256];

    const int tid  = threadIdx.x;
    const int warp = tid >> 5;
    const int lane = tid & 31;

    // Fill replicated code table + LN params (once per CTA)
    {
        const float c = code[tid];
        float4 cv = make_float4(c, c, c, c);
        float4* dst = reinterpret_cast<float4*>(&s_code[tid * REP]);
        dst[0] = cv; dst[1] = cv; dst[2] = cv; dst[3] = cv;
        s_lnw[tid] = __ldg(&reinterpret_cast<const float4*>(lnw)[tid]);
        s_lnb[tid] = __ldg(&reinterpret_cast<const float4*>(lnb)[tid]);
    }
    __syncthreads();

    const float* tab = &s_code[lane & (REP - 1)];
    const int tok0 = (blockIdx.x * 8 + warp) * TPW;

    // Preload all token ids + scales (independent loads, off the chain)
    int   rows[TPW];
    float scales[TPW];
    #pragma unroll
    for (int t = 0; t < TPW; ++t)
        rows[t] = __ldg(&x[tok0 + t]);
    #pragma unroll
    for (int t = 0; t < TPW; ++t)
        scales[t] = __ldg(&absmax[rows[t] >> 2]);

    #pragma unroll
    for (int t = 0; t < TPW; ++t) {
        const int   tok   = tok0 + t;
        const float scale = scales[t];
        const int4* wrow  = reinterpret_cast<const int4*>(w + (long long)rows[t] * D);

        // ---- R5 inner loop, verbatim ----
        int4 q[8];
        #pragma unroll
        for (int i = 0; i < 8; ++i)
            q[i] = __ldg(&wrow[i * 32 + lane]);

        float v[32];
        float sum = 0.0f, sq = 0.0f;
        #pragma unroll
        for (int i = 0; i < 8; ++i) {
            float a = tab[(q[i].x & 255) * REP] * scale;
            float b = tab[(q[i].y & 255) * REP] * scale;
            float c = tab[(q[i].z & 255) * REP] * scale;
            float d = tab[(q[i].w & 255) * REP] * scale;
            v[i*4+0] = a; v[i*4+1] = b; v[i*4+2] = c; v[i*4+3] = d;
            sum += a + b + c + d;
            sq  += a*a + b*b + c*c + d*d;
        }

        #pragma unroll
        for (int off = 16; off > 0; off >>= 1) {
            sum += __shfl_xor_sync(0xFFFFFFFFu, sum, off);
            sq  += __shfl_xor_sync(0xFFFFFFFFu, sq,  off);
        }
        const float mean = sum * (1.0f / D);
        const float rstd = rsqrtf(sq * (1.0f / D) - mean * mean + EPS);

        float4* orow = reinterpret_cast<float4*>(out) + (long long)tok * (D / 4);
        #pragma unroll
        for (int i = 0; i < 8; ++i) {
            const float4 gw = s_lnw[i * 32 + lane];
            const float4 gb = s_lnb[i * 32 + lane];
            float4 o;
            o.x = (v[i*4+0] - mean) * rstd * gw.x + gb.x;
            o.y = (v[i*4+1] - mean) * rstd * gw.y + gb.y;
            o.z = (v[i*4+2] - mean) * rstd * gw.z + gb.z;
            o.w = (v[i*4+3] - mean) * rstd * gw.w + gb.w;
            __stcs(&orow[i * 32 + lane], o);
        }
        // ---- end R5 inner loop ----
    }
}

extern "C" void kernel_launch(void* const* d_in, const int* in_sizes, int n_in,
                              void* d_out, int out_size)
{
    const int*   x      = (const int*)d_in[0];
    const int*   w      = (const int*)d_in[1];
    const float* absmax = (const float*)d_in[2];
    const float* code   = (const float*)d_in[3];
    const float* lnw    = (const float*)d_in[4];
    const float* lnb    = (const float*)d_in[5];
    float*       out    = (float*)d_out;

    const int n_tokens = in_sizes[0];                     // 16384
    const int tokens_per_cta = 8 * TPW;                   // 32
    const int grid = (n_tokens + tokens_per_cta - 1) / tokens_per_cta;  // 512
    emb_ln_kernel<<<grid, 256>>>(x, w, absmax, code, lnw, lnb, out, n_tokens);
}

// round 14
// speedup vs baseline: 1.7750x; 1.7750x over previous
#include <cuda_runtime.h>
#include <cuda_bf16.h>

// FrozenBNBStableEmbedding fused gather+dequant+LayerNorm.
// R14: R5 shape preserved exactly (grid=1024, 256 thr, warp-per-token, 2
// tokens/warp, REP=16 table, inline scale, __stcs) — but the warp's two
// tokens are processed JOINTLY:
//  - both butterflies interleaved (4 chains hide SHFL latency)
//  - ONE epilogue loop loads each LN param float4 once, applies to BOTH
//    tokens -> param smem wavefronts halved (64 -> 32 per token).
// wf/token 176 -> 144. Regs ~80 -> launch_bounds(256,3).

#define D    1024
#define REP  16
#define EPS  1e-5f

__global__ __launch_bounds__(256, 3) void emb_ln_kernel(
    const int*   __restrict__ x,
    const int*   __restrict__ w,
    const float* __restrict__ absmax,
    const float* __restrict__ code,
    const float* __restrict__ lnw,
    const float* __restrict__ lnb,
    float*       __restrict__ out,
    int n_tokens)
{
    __shared__ float  s_code[256 * REP];  // s_code[idx*REP + slot]
    __shared__ float4 s_lnw[256];
    __shared__ float4 s_lnb[256];

    const int tid  = threadIdx.x;
    const int warp = tid >> 5;
    const int lane = tid & 31;

    // Fill replicated code table + LN params (once per CTA)
    {
        const float c = code[tid];
        float4 cv = make_float4(c, c, c, c);
        float4* dst = reinterpret_cast<float4*>(&s_code[tid * REP]);
        dst[0] = cv; dst[1] = cv; dst[2] = cv; dst[3] = cv;
        s_lnw[tid] = __ldg(&reinterpret_cast<const float4*>(lnw)[tid]);
        s_lnb[tid] = __ldg(&reinterpret_cast<const float4*>(lnb)[tid]);
    }
    __syncthreads();

    const float* tab = &s_code[lane & (REP - 1)];
    const int tok0 = (blockIdx.x * 8 + warp) * 2;   // this warp's token pair

    // ---- Token 0: load + dequant + local accum (R5 inner loop) ----
    const int   row0   = __ldg(&x[tok0]);
    const float scale0 = __ldg(&absmax[row0 >> 2]);
    float v0[32];
    float sum0 = 0.0f, sq0 = 0.0f;
    {
        const int4* wrow = reinterpret_cast<const int4*>(w + (long long)row0 * D);
        int4 q[8];
        #pragma unroll
        for (int i = 0; i < 8; ++i)
            q[i] = __ldg(&wrow[i * 32 + lane]);
        #pragma unroll
        for (int i = 0; i < 8; ++i) {
            float a = tab[(q[i].x & 255) * REP] * scale0;
            float b = tab[(q[i].y & 255) * REP] * scale0;
            float c = tab[(q[i].z & 255) * REP] * scale0;
            float d = tab[(q[i].w & 255) * REP] * scale0;
            v0[i*4+0] = a; v0[i*4+1] = b; v0[i*4+2] = c; v0[i*4+3] = d;
            sum0 += a + b + c + d;
            sq0  += a*a + b*b + c*c + d*d;
        }
    }

    // ---- Token 1: load + dequant + local accum ----
    const int   row1   = __ldg(&x[tok0 + 1]);
    const float scale1 = __ldg(&absmax[row1 >> 2]);
    float v1[32];
    float sum1 = 0.0f, sq1 = 0.0f;
    {
        const int4* wrow = reinterpret_cast<const int4*>(w + (long long)row1 * D);
        int4 q[8];
        #pragma unroll
        for (int i = 0; i < 8; ++i)
            q[i] = __ldg(&wrow[i * 32 + lane]);
        #pragma unroll
        for (int i = 0; i < 8; ++i) {
            float a = tab[(q[i].x & 255) * REP] * scale1;
            float b = tab[(q[i].y & 255) * REP] * scale1;
            float c = tab[(q[i].z & 255) * REP] * scale1;
            float d = tab[(q[i].w & 255) * REP] * scale1;
            v1[i*4+0] = a; v1[i*4+1] = b; v1[i*4+2] = c; v1[i*4+3] = d;
            sum1 += a + b + c + d;
            sq1  += a*a + b*b + c*c + d*d;
        }
    }

    // ---- Interleaved butterflies: 4 independent chains hide SHFL latency
    #pragma unroll
    for (int off = 16; off > 0; off >>= 1) {
        sum0 += __shfl_xor_sync(0xFFFFFFFFu, sum0, off);
        sq0  += __shfl_xor_sync(0xFFFFFFFFu, sq0,  off);
        sum1 += __shfl_xor_sync(0xFFFFFFFFu, sum1, off);
        sq1  += __shfl_xor_sync(0xFFFFFFFFu, sq1,  off);
    }
    const float mean0 = sum0 * (1.0f / D);
    const float rstd0 = rsqrtf(sq0 * (1.0f / D) - mean0 * mean0 + EPS);
    const float mean1 = sum1 * (1.0f / D);
    const float rstd1 = rsqrtf(sq1 * (1.0f / D) - mean1 * mean1 + EPS);

    // ---- Shared epilogue: each param float4 loaded ONCE, used twice ----
    float4* orow0 = reinterpret_cast<float4*>(out) + (long long)tok0 * (D / 4);
    float4* orow1 = orow0 + (D / 4);
    #pragma unroll
    for (int i = 0; i < 8; ++i) {
        const float4 gw = s_lnw[i * 32 + lane];
        const float4 gb = s_lnb[i * 32 + lane];
        float4 o;
        o.x = (v0[i*4+0] - mean0) * rstd0 * gw.x + gb.x;
        o.y = (v0[i*4+1] - mean0) * rstd0 * gw.y + gb.y;
        o.z = (v0[i*4+2] - mean0) * rstd0 * gw.z + gb.z;
        o.w = (v0[i*4+3] - mean0) * rstd0 * gw.w + gb.w;
        __stcs(&orow0[i * 32 + lane], o);
        o.x = (v1[i*4+0] - mean1) * rstd1 * gw.x + gb.x;
        o.y = (v1[i*4+1] - mean1) * rstd1 * gw.y + gb.y;
        o.z = (v1[i*4+2] - mean1) * rstd1 * gw.z + gb.z;
        o.w = (v1[i*4+3] - mean1) * rstd1 * gw.w + gb.w;
        __stcs(&orow1[i * 32 + lane], o);
    }
}

extern "C" void kernel_launch(void* const* d_in, const int* in_sizes, int n_in,
                              void* d_out, int out_size)
{
    const int*   x      = (const int*)d_in[0];
    const int*   w      = (const int*)d_in[1];
    const float* absmax = (const float*)d_in[2];
    const float* code   = (const float*)d_in[3];
    const float* lnw    = (const float*)d_in[4];
    const float* lnb    = (const float*)d_in[5];
    float*       out    = (float*)d_out;

    const int n_tokens = in_sizes[0];                 // 16384
    const int grid = (n_tokens + 15) / 16;            // 1024 (16 tokens/CTA)
    emb_ln_kernel<<<grid, 256>>>(x, w, absmax, code, lnw, lnb, out, n_tokens);
}